// round 10
// baseline (speedup 1.0000x reference)
#include <cuda_runtime.h>
#include <cuda_bf16.h>

// Stencil gather: out[b][j][k][{center,up,right,down,left}], edge-replicate.
// Input [16,1024,1024] fp32 (64 MB), output [16,1024,1024,5] (320 MB).
//
// Round-9: issue-cost reduction. R8 falsified the wave theory (occ 6->8
// changed nothing), so the 62% DRAM ceiling is loop-body issue/latency.
//  - Chunk 4 rows per smem stage; drain with 5x LDS.128 + 5x STG.128 per
//    chunk (STG issue 25 -> 3.75 cyc/row, syncwarp amortized 4x).
//  - 4 batched row LDGs per chunk (MLP=4), rolling 2 carried rows.
//  - Same conflict-free 5-stride STS transpose; warp row-base = 640 B =
//    5x128 B, so every STG.128 covers aligned 128B lines.

#define W    1024
#define H    1024
#define NB   16
#define TPB  256
#define RPB  32                  // rows walked per block
#define CH   4                   // rows per smem chunk
#define STRIPS (W / TPB)         // 4
#define BANDS  (H / RPB)         // 32

__global__ __launch_bounds__(TPB, 6)
void stencil5_kernel(const float* __restrict__ x, float* __restrict__ out)
{
    __shared__ float sbuf[TPB / 32][CH * 160];   // 8 warps x 2.56 KB = 20 KB

    const int b     = blockIdx.x;                // img*128 + strip*32 + band
    const int band  =  b        & (BANDS - 1);
    const int strip = (b >> 5)  & (STRIPS - 1);
    const int img   =  b >> 7;

    const int t    = threadIdx.x;
    const int w    = t >> 5;
    const int lane = t & 31;
    const int k    = strip * TPB + t;            // this lane's pixel column
    const int kw   = strip * TPB + (w << 5);     // warp's base column
    const int j0   = band * RPB;

    const float* xim = x + (size_t)img * (H * W);
    const float* xc  = xim + k;                  // column pointer (stride W)

    // Rolling state: rm1 = row j-1 (clamped), r0 = row j.
    float rm1 = xc[(size_t)(j0 ? j0 - 1 : 0) * W];
    float r0  = xc[(size_t)j0 * W];

    float*  obase = out + (((size_t)img * H + j0) * W + kw) * 5;
    float4* b4    = reinterpret_cast<float4*>(sbuf[w]);

    for (int c = 0; c < RPB / CH; ++c) {
        const int jc = j0 + c * CH;

        // 4 batched independent row loads (MLP=4). Only jc+4 can exceed H-1.
        const float n1 = xc[(size_t)(jc + 1) * W];
        const float n2 = xc[(size_t)(jc + 2) * W];
        const float n3 = xc[(size_t)(jc + 3) * W];
        const float n4 = xc[(size_t)(jc + 4 < H ? jc + 4 : H - 1) * W];

        const float cen[CH] = { r0,  n1, n2, n3 };
        const float up [CH] = { rm1, r0, n1, n2 };
        const float dn [CH] = { n1,  n2, n3, n4 };

        float* buf = sbuf[w];
#pragma unroll
        for (int p = 0; p < CH; ++p) {
            const float cc = cen[p];
            float lv = __shfl_up_sync(0xFFFFFFFFu, cc, 1);
            float rv = __shfl_down_sync(0xFFFFFFFFu, cc, 1);
            const float* row = xim + (size_t)(jc + p) * W;
            if (lane == 0)  lv = (k == 0)     ? cc : row[k - 1];  // L1 hit
            if (lane == 31) rv = (k == W - 1) ? cc : row[k + 1];  // L1 hit

            // Transpose to output order {c,u,r,d,l}; stride-5 STS is
            // conflict-free (gcd(5,32)=1).
            const int s = p * 160 + 5 * lane;
            buf[s + 0] = cc;
            buf[s + 1] = up[p];
            buf[s + 2] = rv;
            buf[s + 3] = dn[p];
            buf[s + 4] = lv;
        }
        __syncwarp();

        // Drain 4 rows: 5x LDS.128 + 5x STG.128 per warp.
        // g = m*32+lane indexes 160 float4s; row p = g/40, q = g%40.
#pragma unroll
        for (int m = 0; m < 5; ++m) {
            const int g = (m << 5) + lane;
            const int p = g / 40;
            const int q = g - p * 40;
            const float4 v = b4[g];
            *reinterpret_cast<float4*>(
                obase + (size_t)(c * CH + p) * (W * 5) + (q << 2)) = v;
        }
        __syncwarp();   // buffer reused next chunk

        // Roll two rows across the chunk boundary.
        rm1 = n3;
        r0  = n4;
    }
}

extern "C" void kernel_launch(void* const* d_in, const int* in_sizes, int n_in,
                              void* d_out, int out_size)
{
    const float* x = (const float*)d_in[0];
    float* out = (float*)d_out;
    (void)in_sizes; (void)n_in; (void)out_size;

    stencil5_kernel<<<NB * STRIPS * BANDS, TPB>>>(x, out);
}

// round 11
// speedup vs baseline: 1.1131x; 1.1131x over previous
#include <cuda_runtime.h>
#include <cuda_bf16.h>

// Stencil gather: out[b][j][k][{center,up,right,down,left}], edge-replicate.
// Input [16,1024,1024] fp32 (64 MB), output [16,1024,1024,5] (320 MB).
//
// Round-10: R8 datapath (best: 73.8us) + two latency/write-path cuts:
//  - 2 rows per __syncwarp (sync cost 23 -> 11.5 cyc/row), drain indices
//    fully affine (no div/mod; that was R9's regression).
//  - __stcs streaming stores: output is write-once, evict-first keeps L2
//    available for the rolling row reads.
// Register discipline: scalars only, target <=38 regs (R6/R9 lesson: never
// trade occupancy for issue count).

#define W    1024
#define H    1024
#define NB   16
#define TPB  256
#define RPB  64                  // rows walked per block (even)
#define STRIPS (W / TPB)         // 4
#define BANDS  (H / RPB)         // 16

__global__ __launch_bounds__(TPB, 6)
void stencil5_kernel(const float* __restrict__ x, float* __restrict__ out)
{
    __shared__ float sbuf[TPB / 32][320];      // 2 rows x 160 words per warp

    const int b     = blockIdx.x;              // img*64 + strip*16 + band
    const int band  =  b        & (BANDS - 1);
    const int strip = (b >> 4)  & (STRIPS - 1);
    const int img   =  b >> 6;

    const int t    = threadIdx.x;
    const int w    = t >> 5;
    const int lane = t & 31;
    const int k    = strip * TPB + t;          // this lane's pixel column
    const int kw   = strip * TPB + (w << 5);   // warp's base column
    const int j0   = band * RPB;

    const float* xim = x + (size_t)img * (H * W);
    const float* xc  = xim + k;                // column pointer (stride W)

    // Rolling state: rm1 = row j-1 (clamped), r0 = row j.
    float rm1 = xc[(size_t)(j0 ? j0 - 1 : 0) * W];
    float r0  = xc[(size_t)j0 * W];

    float* op  = out + (((size_t)img * H + j0) * W + kw) * 5;
    float* buf = sbuf[w];

    for (int j = j0; j < j0 + RPB; j += 2) {
        // Two independent row loads (rows j+1, j+2); only j+2 can clamp.
        const float n1 = xc[(size_t)(j + 1) * W];
        const float n2 = xc[(size_t)(j + 2 < H ? j + 2 : H - 1) * W];

        // ---- row j:   c=r0, u=rm1, d=n1 ----
        {
            float lv = __shfl_up_sync(0xFFFFFFFFu, r0, 1);
            float rv = __shfl_down_sync(0xFFFFFFFFu, r0, 1);
            const float* row = xim + (size_t)j * W;
            if (lane == 0)  lv = (k == 0)     ? r0 : row[k - 1];  // L1 hit
            if (lane == 31) rv = (k == W - 1) ? r0 : row[k + 1];  // L1 hit
            const int s = 5 * lane;                // stride-5: conflict-free
            buf[s + 0] = r0;
            buf[s + 1] = rm1;
            buf[s + 2] = rv;
            buf[s + 3] = n1;
            buf[s + 4] = lv;
        }
        // ---- row j+1: c=n1, u=r0, d=n2 ----
        {
            float lv = __shfl_up_sync(0xFFFFFFFFu, n1, 1);
            float rv = __shfl_down_sync(0xFFFFFFFFu, n1, 1);
            const float* row = xim + (size_t)(j + 1) * W;
            if (lane == 0)  lv = (k == 0)     ? n1 : row[k - 1];
            if (lane == 31) rv = (k == W - 1) ? n1 : row[k + 1];
            const int s = 160 + 5 * lane;
            buf[s + 0] = n1;
            buf[s + 1] = r0;
            buf[s + 2] = rv;
            buf[s + 3] = n2;
            buf[s + 4] = lv;
        }
        __syncwarp();

        // Drain both rows: 10 coalesced 128B-line streaming stores.
        // m<5 -> row j (words 0..159), m>=5 -> row j+1 (words 160..319).
#pragma unroll
        for (int m = 0; m < 5; ++m)
            __stcs(&op[(m << 5) + lane], buf[(m << 5) + lane]);
        float* op1 = op + (size_t)W * 5;
#pragma unroll
        for (int m = 0; m < 5; ++m)
            __stcs(&op1[(m << 5) + lane], buf[160 + (m << 5) + lane]);
        __syncwarp();   // buffer reused next pair

        // Roll.
        rm1 = n1; r0 = n2;
        op += (size_t)(W * 5) * 2;
    }
}

extern "C" void kernel_launch(void* const* d_in, const int* in_sizes, int n_in,
                              void* d_out, int out_size)
{
    const float* x = (const float*)d_in[0];
    float* out = (float*)d_out;
    (void)in_sizes; (void)n_in; (void)out_size;

    stencil5_kernel<<<NB * STRIPS * BANDS, TPB>>>(x, out);
}

// round 12
// speedup vs baseline: 1.1186x; 1.0049x over previous
#include <cuda_runtime.h>
#include <cuda_bf16.h>

// Stencil gather: out[b][j][k][{center,up,right,down,left}], edge-replicate.
// Input [16,1024,1024] fp32 (64 MB), output [16,1024,1024,5] (320 MB).
//
// Round-11: R10 datapath (best: 72.4us, 32 regs) with the occupancy
// experiment de-confounded. All prior "occ tests" ran grid=1024, which caps
// residency at ceil(1024/148)=7 blocks/SM regardless of launch bounds.
//  - RPB 32 -> grid 2048: 8 blocks/SM genuinely reachable -> 64 warps/SM.
//  - __launch_bounds__(256, 8).
//  - Band-major block order: adjacent blockIdx = the 4 strips of one row
//    band -> co-resident writers cover one contiguous 20 KB output row
//    window (linear write stream per band).

#define W    1024
#define H    1024
#define NB   16
#define TPB  256
#define RPB  32                  // rows walked per block (even)
#define STRIPS (W / TPB)         // 4
#define BANDS  (H / RPB)         // 32

__global__ __launch_bounds__(TPB, 8)
void stencil5_kernel(const float* __restrict__ x, float* __restrict__ out)
{
    __shared__ float sbuf[TPB / 32][320];      // 2 rows x 160 words per warp

    const int b     = blockIdx.x;              // img*128 + band*4 + strip
    const int strip =  b        & (STRIPS - 1);
    const int band  = (b >> 2)  & (BANDS - 1);
    const int img   =  b >> 7;

    const int t    = threadIdx.x;
    const int w    = t >> 5;
    const int lane = t & 31;
    const int k    = strip * TPB + t;          // this lane's pixel column
    const int kw   = strip * TPB + (w << 5);   // warp's base column
    const int j0   = band * RPB;

    const float* xim = x + (size_t)img * (H * W);
    const float* xc  = xim + k;                // column pointer (stride W)

    // Rolling state: rm1 = row j-1 (clamped), r0 = row j.
    float rm1 = xc[(size_t)(j0 ? j0 - 1 : 0) * W];
    float r0  = xc[(size_t)j0 * W];

    float* op  = out + (((size_t)img * H + j0) * W + kw) * 5;
    float* buf = sbuf[w];

    for (int j = j0; j < j0 + RPB; j += 2) {
        // Two independent row loads (rows j+1, j+2); only j+2 can clamp.
        const float n1 = xc[(size_t)(j + 1) * W];
        const float n2 = xc[(size_t)(j + 2 < H ? j + 2 : H - 1) * W];

        // ---- row j:   c=r0, u=rm1, d=n1 ----
        {
            float lv = __shfl_up_sync(0xFFFFFFFFu, r0, 1);
            float rv = __shfl_down_sync(0xFFFFFFFFu, r0, 1);
            const float* row = xim + (size_t)j * W;
            if (lane == 0)  lv = (k == 0)     ? r0 : row[k - 1];  // L1 hit
            if (lane == 31) rv = (k == W - 1) ? r0 : row[k + 1];  // L1 hit
            const int s = 5 * lane;                // stride-5: conflict-free
            buf[s + 0] = r0;
            buf[s + 1] = rm1;
            buf[s + 2] = rv;
            buf[s + 3] = n1;
            buf[s + 4] = lv;
        }
        // ---- row j+1: c=n1, u=r0, d=n2 ----
        {
            float lv = __shfl_up_sync(0xFFFFFFFFu, n1, 1);
            float rv = __shfl_down_sync(0xFFFFFFFFu, n1, 1);
            const float* row = xim + (size_t)(j + 1) * W;
            if (lane == 0)  lv = (k == 0)     ? n1 : row[k - 1];
            if (lane == 31) rv = (k == W - 1) ? n1 : row[k + 1];
            const int s = 160 + 5 * lane;
            buf[s + 0] = n1;
            buf[s + 1] = r0;
            buf[s + 2] = rv;
            buf[s + 3] = n2;
            buf[s + 4] = lv;
        }
        __syncwarp();

        // Drain both rows: 10 coalesced 128B-line streaming stores.
#pragma unroll
        for (int m = 0; m < 5; ++m)
            __stcs(&op[(m << 5) + lane], buf[(m << 5) + lane]);
        float* op1 = op + (size_t)W * 5;
#pragma unroll
        for (int m = 0; m < 5; ++m)
            __stcs(&op1[(m << 5) + lane], buf[160 + (m << 5) + lane]);
        __syncwarp();   // buffer reused next pair

        // Roll.
        rm1 = n1; r0 = n2;
        op += (size_t)(W * 5) * 2;
    }
}

extern "C" void kernel_launch(void* const* d_in, const int* in_sizes, int n_in,
                              void* d_out, int out_size)
{
    const float* x = (const float*)d_in[0];
    float* out = (float*)d_out;
    (void)in_sizes; (void)n_in; (void)out_size;

    stencil5_kernel<<<NB * STRIPS * BANDS, TPB>>>(x, out);
}